// round 4
// baseline (speedup 1.0000x reference)
#include <cuda_runtime.h>
#include <cuda_fp16.h>
#include <math.h>

// B=64, I=2048, N=16, J=16, M=16, 3 routing iters
#define B_  64
#define I_  2048
#define N_  16
#define J_  16
#define M_  16
#define JM  256
#define CHUNKS 16
#define WPC 8
#define IW (I_/(CHUNKS*WPC))   // 16 i per warp per route pass

// Scratch (device globals). fp16 u_hat = 67 MB.
__device__ __half g_uhat[(size_t)B_ * I_ * JM];     // [b][i][j*16+m]
__device__ float  g_scratch[3 * B_ * JM];           // s0 | s1 | s2
__device__ float  g_osum[B_ * JM];
__device__ int    g_counters[3 * B_];

// ---- packed f32x2 helpers --------------------------------------------------
__device__ __forceinline__ unsigned long long pack2(float lo, float hi) {
    unsigned long long r;
    asm("mov.b64 %0, {%1, %2};" : "=l"(r) : "f"(lo), "f"(hi));
    return r;
}
__device__ __forceinline__ void unpack2(unsigned long long v, float& lo, float& hi) {
    asm("mov.b64 {%0, %1}, %2;" : "=f"(lo), "=f"(hi) : "l"(v));
}
__device__ __forceinline__ void fma2(unsigned long long& acc,
                                     unsigned long long a, unsigned long long b) {
    asm("fma.rn.f32x2 %0, %1, %2, %3;" : "=l"(acc) : "l"(a), "l"(b), "l"(acc));
}

// ---------------------------------------------------------------------------
// K1: u_hat[b,i,j,m] = sum_n inputs[b,i,n] * W[i,j,n,m]   (stored fp16)
__global__ void __launch_bounds__(256) k_uhat(const float* __restrict__ inp,
                                              const float* __restrict__ W) {
    const int i = blockIdx.x;
    const int t = threadIdx.x;
    __shared__ float  Ws[J_ * N_ * M_];
    __shared__ float2 Xs[(B_ / 2) * N_];

    const float* Wp = W + (size_t)i * (J_ * N_ * M_);
    #pragma unroll
    for (int k = t; k < J_ * N_ * M_; k += 256) Ws[k] = Wp[k];
    for (int k = t; k < B_ * N_; k += 256) {
        int b = k >> 4, n = k & 15;
        ((float*)&Xs[(b >> 1) * N_ + n])[b & 1] = inp[((size_t)b * I_ + i) * N_ + n];
    }
    __syncthreads();

    const int j = t >> 4, m = t & 15;
    unsigned long long w2[N_];
    #pragma unroll
    for (int n = 0; n < N_; n++) {
        float w = Ws[j * (N_ * M_) + n * M_ + m];
        w2[n] = pack2(w, w);
    }

    __half* up = g_uhat + (size_t)i * JM + t;
    #pragma unroll 2
    for (int bp = 0; bp < B_ / 2; bp++) {
        const ulonglong2* X22 = (const ulonglong2*)(Xs + bp * N_);
        unsigned long long acc = 0ull;
        #pragma unroll
        for (int q = 0; q < 8; q++) {
            ulonglong2 z = X22[q];
            fma2(acc, z.x, w2[2 * q]);
            fma2(acc, z.y, w2[2 * q + 1]);
        }
        float a0, a1; unpack2(acc, a0, a1);
        up[(size_t)(2 * bp)     * I_ * JM] = __float2half_rn(a0);
        up[(size_t)(2 * bp + 1) * I_ * JM] = __float2half_rn(a1);
    }
}

// ---------------------------------------------------------------------------
// shared squash-update epilogue: last CTA of batch b finalizes the pass
__device__ __forceinline__ void squash_epilogue(int b, float* s_acc, int* cnt,
                                                float pre_scale, int final_pass,
                                                float* out, int ny) {
    __threadfence();
    __shared__ int isLast;
    if (threadIdx.x == 0)
        isLast = (atomicAdd(&cnt[b], 1) == ny - 1);
    __syncthreads();
    if (!isLast) return;
    __threadfence();

    float s = *((volatile float*)&s_acc[b * JM + threadIdx.x]) * pre_scale;
    float n2 = s * s;
    #pragma unroll
    for (int off = 1; off < 16; off <<= 1)
        n2 += __shfl_xor_sync(0xffffffffu, n2, off);
    float v = n2 / (1.f + n2) * rsqrtf(n2 + 1e-8f) * s;

    if (final_pass) out[b * JM + threadIdx.x] = v;
    else            atomicAdd(&g_osum[b * JM + threadIdx.x], v);
}

// ---------------------------------------------------------------------------
// K2: iteration 0 = uniform-c reduction: s0 = (1/16) sum_i u_hat; squash fused.
__global__ void __launch_bounds__(256) k_red0() {
    const int b    = blockIdx.x;
    const int wid  = threadIdx.x >> 5;
    const int lane = threadIdx.x & 31;

    __shared__ float ss[JM];
    ss[threadIdx.x] = 0.f;
    __syncthreads();

    const int i0 = blockIdx.y * 128 + wid * 16;
    const int4* base = (const int4*)(g_uhat + ((size_t)b * I_ + i0) * JM);

    float acc[8];
    #pragma unroll
    for (int k = 0; k < 8; k++) acc[k] = 0.f;
    #pragma unroll
    for (int blk = 0; blk < 4; blk++) {
        int4 v[4];
        #pragma unroll
        for (int r = 0; r < 4; r++)
            v[r] = base[(blk * 4 + r) * (JM / 8) + lane];
        #pragma unroll
        for (int r = 0; r < 4; r++) {
            const __half2* hp = (const __half2*)&v[r];
            #pragma unroll
            for (int q = 0; q < 4; q++) {
                float2 f = __half22float2(hp[q]);
                acc[2 * q] += f.x; acc[2 * q + 1] += f.y;
            }
        }
    }
    float* sp = ss + lane * 8;
    #pragma unroll
    for (int k = 0; k < 8; k++) atomicAdd(sp + k, acc[k]);
    __syncthreads();
    atomicAdd(&g_scratch[b * JM + threadIdx.x], ss[threadIdx.x]);

    squash_epilogue(b, g_scratch, g_counters, 1.f / 16.f, 0, nullptr, gridDim.y);
}

// ---------------------------------------------------------------------------
// K3: routing pass, j-per-lane mapping.
// Lane l: j = l&15, half h = l>>4. Lane processes i = i0 + 2*ii + h, reading
// its j's 16-half row chunk (32B) and computing the logit locally (no shuffle).
// Softmax over j = one 4-stage butterfly inside the 16-lane group.
__global__ void __launch_bounds__(256) k_route(float* __restrict__ s_acc,
                                               int* __restrict__ cnt,
                                               float* __restrict__ out,
                                               int final_pass) {
    const int b    = blockIdx.x;
    const int wid  = threadIdx.x >> 5;
    const int lane = threadIdx.x & 31;
    const int j    = lane & 15;
    const int h    = lane >> 4;

    __shared__ float os[JM];
    __shared__ float ss[JM];
    os[threadIdx.x] = g_osum[b * JM + threadIdx.x];
    ss[threadIdx.x] = 0.f;
    __syncthreads();

    float o[16];
    #pragma unroll
    for (int k = 0; k < 16; k++) o[k] = os[j * 16 + k];

    float acc[16];
    #pragma unroll
    for (int k = 0; k < 16; k++) acc[k] = 0.f;

    const int i0 = (blockIdx.y * WPC + wid) * IW;
    // lane's pointer: row (i0+h), halves [j*16, j*16+16) -> 2 uint4
    const uint4* lp = (const uint4*)(g_uhat + ((size_t)b * I_ + i0 + h) * JM) + j * 2;
    const int STRIDE = 2 * (JM / 8);    // 2 rows in uint4 units = 64

    uint4 ra = lp[0], rb = lp[1];       // prologue load (ii = 0)
    #pragma unroll
    for (int ii = 0; ii < IW / 2; ii++) {
        uint4 na, nb;
        if (ii < IW / 2 - 1) { na = lp[(ii + 1) * STRIDE]; nb = lp[(ii + 1) * STRIDE + 1]; }

        float u[16];
        {
            const __half2* ha = (const __half2*)&ra;
            const __half2* hb = (const __half2*)&rb;
            #pragma unroll
            for (int q = 0; q < 4; q++) {
                float2 f = __half22float2(ha[q]);
                u[2 * q] = f.x; u[2 * q + 1] = f.y;
                float2 g = __half22float2(hb[q]);
                u[8 + 2 * q] = g.x; u[8 + 2 * q + 1] = g.y;
            }
        }
        float p = 0.f;
        #pragma unroll
        for (int k = 0; k < 16; k++) p += u[k] * o[k];
        p = __expf(p);                          // logits bounded; no max-sub
        float sum = p;
        #pragma unroll
        for (int off = 1; off < 16; off <<= 1)  // softmax denom over 16 j's
            sum += __shfl_xor_sync(0xffffffffu, sum, off);
        float c = __fdividef(p, sum);
        #pragma unroll
        for (int k = 0; k < 16; k++) acc[k] += c * u[k];

        ra = na; rb = nb;
    }

    // combine warp halves (same j, disjoint i's)
    #pragma unroll
    for (int k = 0; k < 16; k++)
        acc[k] += __shfl_xor_sync(0xffffffffu, acc[k], 16);

    if (h == 0) {
        float* sp = ss + j * 16;
        #pragma unroll
        for (int k = 0; k < 16; k++) atomicAdd(sp + k, acc[k]);
    }
    __syncthreads();
    atomicAdd(&s_acc[b * JM + threadIdx.x], ss[threadIdx.x]);

    squash_epilogue(b, s_acc, cnt, 1.f, final_pass, out, gridDim.y);
}

// ---------------------------------------------------------------------------
extern "C" void kernel_launch(void* const* d_in, const int* in_sizes, int n_in,
                              void* d_out, int out_size) {
    const float* inp = (const float*)d_in[0];   // [B, I, N]
    const float* W   = (const float*)d_in[1];   // [I, J, N, M]
    float* out = (float*)d_out;                 // [B, J, M]

    void *p_scr, *p_cnt, *p_os;
    cudaGetSymbolAddress(&p_scr, g_scratch);
    cudaGetSymbolAddress(&p_cnt, g_counters);
    cudaGetSymbolAddress(&p_os,  g_osum);
    cudaMemsetAsync(p_scr, 0, 3 * B_ * JM * sizeof(float));
    cudaMemsetAsync(p_cnt, 0, 3 * B_ * sizeof(int));
    cudaMemsetAsync(p_os,  0, B_ * JM * sizeof(float));

    float* s1 = (float*)p_scr + B_ * JM;
    float* s2 = (float*)p_scr + 2 * B_ * JM;
    int* c1 = (int*)p_cnt + B_;
    int* c2 = (int*)p_cnt + 2 * B_;

    dim3 rg(B_, CHUNKS);
    k_uhat<<<I_, 256>>>(inp, W);
    k_red0<<<dim3(B_, 16), 256>>>();            // iter 0 (uniform c) + squash
    k_route<<<rg, 256>>>(s1, c1, out, 0);       // iter 1
    k_route<<<rg, 256>>>(s2, c2, out, 1);       // iter 2 -> d_out
}

// round 5
// speedup vs baseline: 1.0532x; 1.0532x over previous
#include <cuda_runtime.h>
#include <cuda_fp16.h>
#include <math.h>

// B=64, I=2048, N=16, J=16, M=16, 3 routing iters
#define B_  64
#define I_  2048
#define N_  16
#define J_  16
#define M_  16
#define JM  256
#define CHUNKS 32
#define WPC 8
#define IW (I_/(CHUNKS*WPC))   // = 8 i per warp per route pass (single batch)

// Scratch (device globals). fp16 u_hat = 67 MB (L2-resident on replay).
__device__ __half g_uhat[(size_t)B_ * I_ * JM];     // [b][i][j*16+m]
__device__ float  g_scratch[3 * B_ * JM];           // s0 | s1 | s2
__device__ float  g_osum[B_ * JM];
__device__ int    g_counters[3 * B_];

// ---- packed f32x2 helpers --------------------------------------------------
__device__ __forceinline__ unsigned long long pack2(float lo, float hi) {
    unsigned long long r;
    asm("mov.b64 %0, {%1, %2};" : "=l"(r) : "f"(lo), "f"(hi));
    return r;
}
__device__ __forceinline__ void unpack2(unsigned long long v, float& lo, float& hi) {
    asm("mov.b64 {%0, %1}, %2;" : "=f"(lo), "=f"(hi) : "l"(v));
}
__device__ __forceinline__ void fma2(unsigned long long& acc,
                                     unsigned long long a, unsigned long long b) {
    asm("fma.rn.f32x2 %0, %1, %2, %3;" : "=l"(acc) : "l"(a), "l"(b), "l"(acc));
}

// ---------------------------------------------------------------------------
// K1: u_hat[b,i,j,m] = sum_n inputs[b,i,n] * W[i,j,n,m]   (stored fp16)
__global__ void __launch_bounds__(256) k_uhat(const float* __restrict__ inp,
                                              const float* __restrict__ W) {
    const int i = blockIdx.x;
    const int t = threadIdx.x;
    __shared__ float  Ws[J_ * N_ * M_];
    __shared__ float2 Xs[(B_ / 2) * N_];

    const float* Wp = W + (size_t)i * (J_ * N_ * M_);
    #pragma unroll
    for (int k = t; k < J_ * N_ * M_; k += 256) Ws[k] = Wp[k];
    for (int k = t; k < B_ * N_; k += 256) {
        int b = k >> 4, n = k & 15;
        ((float*)&Xs[(b >> 1) * N_ + n])[b & 1] = inp[((size_t)b * I_ + i) * N_ + n];
    }
    __syncthreads();

    const int j = t >> 4, m = t & 15;
    unsigned long long w2[N_];
    #pragma unroll
    for (int n = 0; n < N_; n++) {
        float w = Ws[j * (N_ * M_) + n * M_ + m];
        w2[n] = pack2(w, w);
    }

    __half* up = g_uhat + (size_t)i * JM + t;
    #pragma unroll 2
    for (int bp = 0; bp < B_ / 2; bp++) {
        const ulonglong2* X22 = (const ulonglong2*)(Xs + bp * N_);
        unsigned long long acc = 0ull;
        #pragma unroll
        for (int q = 0; q < 8; q++) {
            ulonglong2 z = X22[q];
            fma2(acc, z.x, w2[2 * q]);
            fma2(acc, z.y, w2[2 * q + 1]);
        }
        float a0, a1; unpack2(acc, a0, a1);
        up[(size_t)(2 * bp)     * I_ * JM] = __float2half_rn(a0);
        up[(size_t)(2 * bp + 1) * I_ * JM] = __float2half_rn(a1);
    }
}

// ---------------------------------------------------------------------------
// shared squash-update epilogue: last CTA of batch b finalizes the pass
__device__ __forceinline__ void squash_epilogue(int b, float* s_acc, int* cnt,
                                                float pre_scale, int final_pass,
                                                float* out, int ny) {
    __threadfence();
    __shared__ int isLast;
    if (threadIdx.x == 0)
        isLast = (atomicAdd(&cnt[b], 1) == ny - 1);
    __syncthreads();
    if (!isLast) return;
    __threadfence();

    float s = *((volatile float*)&s_acc[b * JM + threadIdx.x]) * pre_scale;
    float n2 = s * s;
    #pragma unroll
    for (int off = 1; off < 16; off <<= 1)
        n2 += __shfl_xor_sync(0xffffffffu, n2, off);
    float v = n2 / (1.f + n2) * rsqrtf(n2 + 1e-8f) * s;

    if (final_pass) out[b * JM + threadIdx.x] = v;
    else            atomicAdd(&g_osum[b * JM + threadIdx.x], v);
}

// ---------------------------------------------------------------------------
// K2: iteration 0 = uniform-c reduction: s0 = (1/16) sum_i u_hat; squash fused.
__global__ void __launch_bounds__(256) k_red0() {
    const int b    = blockIdx.x;
    const int wid  = threadIdx.x >> 5;
    const int lane = threadIdx.x & 31;

    __shared__ float ss[JM];
    ss[threadIdx.x] = 0.f;
    __syncthreads();

    const int i0 = blockIdx.y * 128 + wid * 16;
    const int4* base = (const int4*)(g_uhat + ((size_t)b * I_ + i0) * JM);

    float acc[8];
    #pragma unroll
    for (int k = 0; k < 8; k++) acc[k] = 0.f;
    #pragma unroll
    for (int blk = 0; blk < 4; blk++) {
        int4 v[4];
        #pragma unroll
        for (int r = 0; r < 4; r++)
            v[r] = base[(blk * 4 + r) * (JM / 8) + lane];
        #pragma unroll
        for (int r = 0; r < 4; r++) {
            const __half2* hp = (const __half2*)&v[r];
            #pragma unroll
            for (int q = 0; q < 4; q++) {
                float2 f = __half22float2(hp[q]);
                acc[2 * q] += f.x; acc[2 * q + 1] += f.y;
            }
        }
    }
    float* sp = ss + lane * 8;
    #pragma unroll
    for (int k = 0; k < 8; k++) atomicAdd(sp + k, acc[k]);
    __syncthreads();
    atomicAdd(&g_scratch[b * JM + threadIdx.x], ss[threadIdx.x]);

    squash_epilogue(b, g_scratch, g_counters, 1.f / 16.f, 0, nullptr, gridDim.y);
}

// ---------------------------------------------------------------------------
// K3: routing pass (iters 1,2), R3 mapping: lane l owns (j=l>>1, m-half l&1),
// 8-wide batched softmax (ILP-8 shuffle/exp pipelines), single batch per warp.
__global__ void __launch_bounds__(256) k_route(float* __restrict__ s_acc,
                                               int* __restrict__ cnt,
                                               float* __restrict__ out,
                                               int final_pass) {
    const int b    = blockIdx.x;
    const int wid  = threadIdx.x >> 5;
    const int lane = threadIdx.x & 31;

    __shared__ float os[JM];
    __shared__ float ss[JM];
    os[threadIdx.x] = g_osum[b * JM + threadIdx.x];
    ss[threadIdx.x] = 0.f;
    __syncthreads();

    const float L2E = 1.4426950408889634f;    // log2(e): exp(x) = exp2(x*L2E)
    float o[8];
    #pragma unroll
    for (int k = 0; k < 8; k++) o[k] = os[lane * 8 + k] * L2E;

    float acc[8];
    #pragma unroll
    for (int k = 0; k < 8; k++) acc[k] = 0.f;

    const int i0 = (blockIdx.y * WPC + wid) * IW;
    const int4* base = (const int4*)(g_uhat + ((size_t)b * I_ + i0) * JM);

    // single batch of IW=8 rows, all loads in flight up front
    int4 v[8];
    #pragma unroll
    for (int r = 0; r < 8; r++)
        v[r] = base[r * (JM / 8) + lane];

    float p[8];
    #pragma unroll
    for (int r = 0; r < 8; r++) {
        const __half2* hp = (const __half2*)&v[r];
        float2 f0 = __half22float2(hp[0]), f1 = __half22float2(hp[1]);
        float2 f2 = __half22float2(hp[2]), f3 = __half22float2(hp[3]);
        p[r] = f0.x*o[0] + f0.y*o[1] + f1.x*o[2] + f1.y*o[3]
             + f2.x*o[4] + f2.y*o[5] + f3.x*o[6] + f3.y*o[7];
    }
    #pragma unroll
    for (int r = 0; r < 8; r++) p[r] += __shfl_xor_sync(0xffffffffu, p[r], 1);
    #pragma unroll
    for (int r = 0; r < 8; r++) p[r] = exp2f(p[r]);   // logits bounded; no max-sub
    float sum[8];
    #pragma unroll
    for (int r = 0; r < 8; r++) sum[r] = p[r];
    #pragma unroll
    for (int off = 2; off < 32; off <<= 1) {
        #pragma unroll
        for (int r = 0; r < 8; r++)
            sum[r] += __shfl_xor_sync(0xffffffffu, sum[r], off);
    }
    #pragma unroll
    for (int r = 0; r < 8; r++) {
        float c = __fdividef(p[r], sum[r]);
        const __half2* hp = (const __half2*)&v[r];
        float2 f0 = __half22float2(hp[0]), f1 = __half22float2(hp[1]);
        float2 f2 = __half22float2(hp[2]), f3 = __half22float2(hp[3]);
        acc[0] += c * f0.x; acc[1] += c * f0.y;
        acc[2] += c * f1.x; acc[3] += c * f1.y;
        acc[4] += c * f2.x; acc[5] += c * f2.y;
        acc[6] += c * f3.x; acc[7] += c * f3.y;
    }

    float* sp = ss + lane * 8;
    #pragma unroll
    for (int k = 0; k < 8; k++) atomicAdd(sp + k, acc[k]);
    __syncthreads();
    atomicAdd(&s_acc[b * JM + threadIdx.x], ss[threadIdx.x]);

    squash_epilogue(b, s_acc, cnt, 1.f, final_pass, out, gridDim.y);
}

// ---------------------------------------------------------------------------
extern "C" void kernel_launch(void* const* d_in, const int* in_sizes, int n_in,
                              void* d_out, int out_size) {
    const float* inp = (const float*)d_in[0];   // [B, I, N]
    const float* W   = (const float*)d_in[1];   // [I, J, N, M]
    float* out = (float*)d_out;                 // [B, J, M]

    void *p_scr, *p_cnt, *p_os;
    cudaGetSymbolAddress(&p_scr, g_scratch);
    cudaGetSymbolAddress(&p_cnt, g_counters);
    cudaGetSymbolAddress(&p_os,  g_osum);
    cudaMemsetAsync(p_scr, 0, 3 * B_ * JM * sizeof(float));
    cudaMemsetAsync(p_cnt, 0, 3 * B_ * sizeof(int));
    cudaMemsetAsync(p_os,  0, B_ * JM * sizeof(float));

    float* s1 = (float*)p_scr + B_ * JM;
    float* s2 = (float*)p_scr + 2 * B_ * JM;
    int* c1 = (int*)p_cnt + B_;
    int* c2 = (int*)p_cnt + 2 * B_;

    dim3 rg(B_, CHUNKS);
    k_uhat<<<I_, 256>>>(inp, W);
    k_red0<<<dim3(B_, 16), 256>>>();            // iter 0 (uniform c) + squash
    k_route<<<rg, 256>>>(s1, c1, out, 0);       // iter 1
    k_route<<<rg, 256>>>(s2, c2, out, 1);       // iter 2 -> d_out
}

// round 6
// speedup vs baseline: 1.4951x; 1.4195x over previous
#include <cuda_runtime.h>
#include <cuda_fp16.h>
#include <math.h>

// B=64, I=2048, N=16, J=16, M=16, 3 routing iters
#define B_  64
#define I_  2048
#define N_  16
#define J_  16
#define M_  16
#define JM  256
#define CHUNKS 16
#define WPC 8
#define IW (I_/(CHUNKS*WPC))   // = 16 i per warp per route pass

// Scratch (device globals). fp16 u_hat = 67 MB.
__device__ __half g_uhat[(size_t)B_ * I_ * JM];     // [b][i][j*16+m]
__device__ float  g_scratch[3 * B_ * JM];           // s0 | s1 | s2
__device__ float  g_osum[B_ * JM];
__device__ int    g_counters[3 * B_];

// ---- packed f32x2 helpers --------------------------------------------------
__device__ __forceinline__ unsigned long long pack2(float lo, float hi) {
    unsigned long long r;
    asm("mov.b64 %0, {%1, %2};" : "=l"(r) : "f"(lo), "f"(hi));
    return r;
}
__device__ __forceinline__ void unpack2(unsigned long long v, float& lo, float& hi) {
    asm("mov.b64 {%0, %1}, %2;" : "=f"(lo), "=f"(hi) : "l"(v));
}
__device__ __forceinline__ void fma2(unsigned long long& acc,
                                     unsigned long long a, unsigned long long b) {
    asm("fma.rn.f32x2 %0, %1, %2, %3;" : "=l"(acc) : "l"(a), "l"(b), "l"(acc));
}

// ---------------------------------------------------------------------------
// K1: u_hat[b,i,j,m] = sum_n inputs[b,i,n] * W[i,j,n,m]   (stored fp16)
__global__ void __launch_bounds__(256) k_uhat(const float* __restrict__ inp,
                                              const float* __restrict__ W) {
    const int i = blockIdx.x;
    const int t = threadIdx.x;
    __shared__ float  Ws[J_ * N_ * M_];
    __shared__ float2 Xs[(B_ / 2) * N_];

    const float* Wp = W + (size_t)i * (J_ * N_ * M_);
    #pragma unroll
    for (int k = t; k < J_ * N_ * M_; k += 256) Ws[k] = Wp[k];
    for (int k = t; k < B_ * N_; k += 256) {
        int b = k >> 4, n = k & 15;
        ((float*)&Xs[(b >> 1) * N_ + n])[b & 1] = inp[((size_t)b * I_ + i) * N_ + n];
    }
    __syncthreads();

    const int j = t >> 4, m = t & 15;
    unsigned long long w2[N_];
    #pragma unroll
    for (int n = 0; n < N_; n++) {
        float w = Ws[j * (N_ * M_) + n * M_ + m];
        w2[n] = pack2(w, w);
    }

    __half* up = g_uhat + (size_t)i * JM + t;
    #pragma unroll 2
    for (int bp = 0; bp < B_ / 2; bp++) {
        const ulonglong2* X22 = (const ulonglong2*)(Xs + bp * N_);
        unsigned long long acc = 0ull;
        #pragma unroll
        for (int q = 0; q < 8; q++) {
            ulonglong2 z = X22[q];
            fma2(acc, z.x, w2[2 * q]);
            fma2(acc, z.y, w2[2 * q + 1]);
        }
        float a0, a1; unpack2(acc, a0, a1);
        up[(size_t)(2 * bp)     * I_ * JM] = __float2half_rn(a0);
        up[(size_t)(2 * bp + 1) * I_ * JM] = __float2half_rn(a1);
    }
}

// ---------------------------------------------------------------------------
// shared squash-update epilogue: last CTA of batch b finalizes the pass
__device__ __forceinline__ void squash_epilogue(int b, float* s_acc, int* cnt,
                                                float pre_scale, int final_pass,
                                                float* out, int ny) {
    __threadfence();
    __shared__ int isLast;
    if (threadIdx.x == 0)
        isLast = (atomicAdd(&cnt[b], 1) == ny - 1);
    __syncthreads();
    if (!isLast) return;
    __threadfence();

    float s = *((volatile float*)&s_acc[b * JM + threadIdx.x]) * pre_scale;
    float n2 = s * s;
    #pragma unroll
    for (int off = 1; off < 16; off <<= 1)
        n2 += __shfl_xor_sync(0xffffffffu, n2, off);
    float v = n2 / (1.f + n2) * rsqrtf(n2 + 1e-8f) * s;

    if (final_pass) out[b * JM + threadIdx.x] = v;
    else            atomicAdd(&g_osum[b * JM + threadIdx.x], v);
}

// ---------------------------------------------------------------------------
// per-warp partial stores + cross-warp tree reduce + one global REDG / thread.
// Each warp covers slots lane*8..lane*8+7 bijectively -> NO smem atomics.
__device__ __forceinline__ void reduce_epilogue(int b, float* s_acc,
                                                float (&ws)[WPC][JM],
                                                const float* acc,
                                                int wid, int lane) {
    float4* dst = (float4*)&ws[wid][lane * 8];
    dst[0] = make_float4(acc[0], acc[1], acc[2], acc[3]);
    dst[1] = make_float4(acc[4], acc[5], acc[6], acc[7]);
    __syncthreads();
    float tsum = 0.f;
    #pragma unroll
    for (int w = 0; w < WPC; w++) tsum += ws[w][threadIdx.x];
    atomicAdd(&s_acc[b * JM + threadIdx.x], tsum);
}

// ---------------------------------------------------------------------------
// K2: iteration 0 = uniform-c reduction: s0 = (1/16) sum_i u_hat; squash fused.
__global__ void __launch_bounds__(256) k_red0() {
    const int b    = blockIdx.x;
    const int wid  = threadIdx.x >> 5;
    const int lane = threadIdx.x & 31;

    __shared__ float ws[WPC][JM];   // 8 KB per-warp partials

    const int i0 = blockIdx.y * 128 + wid * 16;
    const int4* base = (const int4*)(g_uhat + ((size_t)b * I_ + i0) * JM);

    float acc[8];
    #pragma unroll
    for (int k = 0; k < 8; k++) acc[k] = 0.f;
    #pragma unroll
    for (int blk = 0; blk < 4; blk++) {
        int4 v[4];
        #pragma unroll
        for (int r = 0; r < 4; r++)
            v[r] = base[(blk * 4 + r) * (JM / 8) + lane];
        #pragma unroll
        for (int r = 0; r < 4; r++) {
            const __half2* hp = (const __half2*)&v[r];
            #pragma unroll
            for (int q = 0; q < 4; q++) {
                float2 f = __half22float2(hp[q]);
                acc[2 * q] += f.x; acc[2 * q + 1] += f.y;
            }
        }
    }
    reduce_epilogue(b, g_scratch, ws, acc, wid, lane);
    squash_epilogue(b, g_scratch, g_counters, 1.f / 16.f, 0, nullptr, gridDim.y);
}

// ---------------------------------------------------------------------------
// K3: routing pass (iters 1,2): lane l owns (j=l>>1, m-half l&1),
// 8-wide batched softmax (ILP-8 shuffle/exp2 pipelines), 2 batches per warp.
__global__ void __launch_bounds__(256) k_route(float* __restrict__ s_acc,
                                               int* __restrict__ cnt,
                                               float* __restrict__ out,
                                               int final_pass) {
    const int b    = blockIdx.x;
    const int wid  = threadIdx.x >> 5;
    const int lane = threadIdx.x & 31;

    __shared__ float os[JM];
    __shared__ float ws[WPC][JM];
    os[threadIdx.x] = g_osum[b * JM + threadIdx.x];
    __syncthreads();

    const float L2E = 1.4426950408889634f;
    float o[8];
    #pragma unroll
    for (int k = 0; k < 8; k++) o[k] = os[lane * 8 + k] * L2E;

    float acc[8];
    #pragma unroll
    for (int k = 0; k < 8; k++) acc[k] = 0.f;

    const int i0 = (blockIdx.y * WPC + wid) * IW;
    const int4* base = (const int4*)(g_uhat + ((size_t)b * I_ + i0) * JM);

    #pragma unroll
    for (int batch = 0; batch < IW / 8; batch++) {
        int4 v[8];
        #pragma unroll
        for (int r = 0; r < 8; r++)
            v[r] = base[(batch * 8 + r) * (JM / 8) + lane];

        float p[8];
        #pragma unroll
        for (int r = 0; r < 8; r++) {
            const __half2* hp = (const __half2*)&v[r];
            float2 f0 = __half22float2(hp[0]), f1 = __half22float2(hp[1]);
            float2 f2 = __half22float2(hp[2]), f3 = __half22float2(hp[3]);
            p[r] = f0.x*o[0] + f0.y*o[1] + f1.x*o[2] + f1.y*o[3]
                 + f2.x*o[4] + f2.y*o[5] + f3.x*o[6] + f3.y*o[7];
        }
        #pragma unroll
        for (int r = 0; r < 8; r++) p[r] += __shfl_xor_sync(0xffffffffu, p[r], 1);
        #pragma unroll
        for (int r = 0; r < 8; r++) p[r] = exp2f(p[r]);   // bounded; no max-sub
        float sum[8];
        #pragma unroll
        for (int r = 0; r < 8; r++) sum[r] = p[r];
        #pragma unroll
        for (int off = 2; off < 32; off <<= 1) {
            #pragma unroll
            for (int r = 0; r < 8; r++)
                sum[r] += __shfl_xor_sync(0xffffffffu, sum[r], off);
        }
        #pragma unroll
        for (int r = 0; r < 8; r++) {
            float c = __fdividef(p[r], sum[r]);
            const __half2* hp = (const __half2*)&v[r];
            float2 f0 = __half22float2(hp[0]), f1 = __half22float2(hp[1]);
            float2 f2 = __half22float2(hp[2]), f3 = __half22float2(hp[3]);
            acc[0] += c * f0.x; acc[1] += c * f0.y;
            acc[2] += c * f1.x; acc[3] += c * f1.y;
            acc[4] += c * f2.x; acc[5] += c * f2.y;
            acc[6] += c * f3.x; acc[7] += c * f3.y;
        }
    }

    reduce_epilogue(b, s_acc, ws, acc, wid, lane);
    squash_epilogue(b, s_acc, cnt, 1.f, final_pass, out, gridDim.y);
}

// ---------------------------------------------------------------------------
extern "C" void kernel_launch(void* const* d_in, const int* in_sizes, int n_in,
                              void* d_out, int out_size) {
    const float* inp = (const float*)d_in[0];   // [B, I, N]
    const float* W   = (const float*)d_in[1];   // [I, J, N, M]
    float* out = (float*)d_out;                 // [B, J, M]

    void *p_scr, *p_cnt, *p_os;
    cudaGetSymbolAddress(&p_scr, g_scratch);
    cudaGetSymbolAddress(&p_cnt, g_counters);
    cudaGetSymbolAddress(&p_os,  g_osum);
    cudaMemsetAsync(p_scr, 0, 3 * B_ * JM * sizeof(float));
    cudaMemsetAsync(p_cnt, 0, 3 * B_ * sizeof(int));
    cudaMemsetAsync(p_os,  0, B_ * JM * sizeof(float));

    float* s1 = (float*)p_scr + B_ * JM;
    float* s2 = (float*)p_scr + 2 * B_ * JM;
    int* c1 = (int*)p_cnt + B_;
    int* c2 = (int*)p_cnt + 2 * B_;

    dim3 rg(B_, CHUNKS);
    k_uhat<<<I_, 256>>>(inp, W);
    k_red0<<<dim3(B_, 16), 256>>>();            // iter 0 (uniform c) + squash
    k_route<<<rg, 256>>>(s1, c1, out, 0);       // iter 1
    k_route<<<rg, 256>>>(s2, c2, out, 1);       // iter 2 -> d_out
}

// round 8
// speedup vs baseline: 1.9371x; 1.2956x over previous
#include <cuda_runtime.h>
#include <cuda_fp16.h>
#include <stdint.h>
#include <math.h>

// B=64, I=2048, N=16, J=16, M=16, 3 routing iters
#define B_  64
#define I_  2048
#define N_  16
#define J_  16
#define M_  16
#define JM  256
#define CHUNKS 16
#define WPC 8
#define IW (I_/(CHUNKS*WPC))   // = 16 i per warp per route pass

// Scratch (device globals). fp16 u_hat = 67 MB.
__device__ __half g_uhat[(size_t)B_ * I_ * JM];     // [b][i][j*16+m]
__device__ float  g_scratch[3 * B_ * JM];           // s0 | s1 | s2
__device__ float  g_osum[B_ * JM];
__device__ int    g_counters[3 * B_];

// ---------------------------------------------------------------------------
// K1 (HMMA): per CTA = one input capsule i.
//   D[b, jm] = sum_n x[b,i,n] * W[i][jm/16][n][jm%16]
//   = X(64x16,f16) @ Wt(16x256,f16), via mma.sync m16n8k16 (fp32 accum).
// Layout: Xh[b][n] rows padded to 18 halves; Wh[jm][n] (B col-major) padded 18;
// Dst[b][jm] padded to 264 halves (conflict-free frag stores), coalesced out.
#define XPAD 18
#define WPAD 18
#define DPAD 264
__global__ void __launch_bounds__(256) k_uhat(const float* __restrict__ inp,
                                              const float* __restrict__ W) {
    __shared__ __half Xh[B_ * XPAD];
    __shared__ __half Wh[JM * WPAD];
    __shared__ __half Dst[B_ * DPAD];

    const int i = blockIdx.x;
    const int t = threadIdx.x;

    // load X[b, i, :] (64 x 16 f32) -> Xh fp16
    {
        int b = t >> 2, n0 = (t & 3) * 4;
        float4 x = *(const float4*)(inp + ((size_t)b * I_ + i) * N_ + n0);
        Xh[b * XPAD + n0 + 0] = __float2half_rn(x.x);
        Xh[b * XPAD + n0 + 1] = __float2half_rn(x.y);
        Xh[b * XPAD + n0 + 2] = __float2half_rn(x.z);
        Xh[b * XPAD + n0 + 3] = __float2half_rn(x.w);
    }
    // load W[i] (4096 f32, [j][n][m]) -> Wh[jm][n] fp16 (transposed)
    {
        const float4* W4 = (const float4*)(W + (size_t)i * 4096);
        #pragma unroll
        for (int k = 0; k < 4; k++) {
            int e = t + k * 256;             // float4 index
            float4 w = W4[e];
            int idx = e * 4;
            int j = idx >> 8, n = (idx >> 4) & 15, m = idx & 15;
            int jm = j * 16 + m;
            Wh[(jm + 0) * WPAD + n] = __float2half_rn(w.x);
            Wh[(jm + 1) * WPAD + n] = __float2half_rn(w.y);
            Wh[(jm + 2) * WPAD + n] = __float2half_rn(w.z);
            Wh[(jm + 3) * WPAD + n] = __float2half_rn(w.w);
        }
    }
    __syncthreads();

    const int w = t >> 5, lane = t & 31;
    const int g = lane >> 2, q = lane & 3;

    // B fragments: warp w owns N-tiles nt = 4w..4w+3 (jm cols nt*8+g)
    uint32_t bf[4][2];
    #pragma unroll
    for (int f = 0; f < 4; f++) {
        int jm = (w * 4 + f) * 8 + g;
        bf[f][0] = *(const uint32_t*)&Wh[jm * WPAD + q * 2];
        bf[f][1] = *(const uint32_t*)&Wh[jm * WPAD + q * 2 + 8];
    }
    #pragma unroll
    for (int mt = 0; mt < 4; mt++) {
        int r0 = mt * 16 + g, r1 = r0 + 8;
        uint32_t a0 = *(const uint32_t*)&Xh[r0 * XPAD + q * 2];
        uint32_t a1 = *(const uint32_t*)&Xh[r1 * XPAD + q * 2];
        uint32_t a2 = *(const uint32_t*)&Xh[r0 * XPAD + q * 2 + 8];
        uint32_t a3 = *(const uint32_t*)&Xh[r1 * XPAD + q * 2 + 8];
        #pragma unroll
        for (int f = 0; f < 4; f++) {
            float d0 = 0.f, d1 = 0.f, d2 = 0.f, d3 = 0.f;
            asm volatile(
                "mma.sync.aligned.m16n8k16.row.col.f32.f16.f16.f32 "
                "{%0,%1,%2,%3}, {%4,%5,%6,%7}, {%8,%9}, {%0,%1,%2,%3};"
                : "+f"(d0), "+f"(d1), "+f"(d2), "+f"(d3)
                : "r"(a0), "r"(a1), "r"(a2), "r"(a3),
                  "r"(bf[f][0]), "r"(bf[f][1]));
            int jm = (w * 4 + f) * 8 + q * 2;
            *(__half2*)&Dst[r0 * DPAD + jm] = __floats2half2_rn(d0, d1);
            *(__half2*)&Dst[r1 * DPAD + jm] = __floats2half2_rn(d2, d3);
        }
    }
    __syncthreads();

    // coalesced copy-out: one warp per b-row per iter (512B contiguous)
    __half* up = g_uhat + (size_t)i * JM;
    #pragma unroll
    for (int k = 0; k < 8; k++) {
        int e = t + k * 256;                 // uint4 id, 2048 total
        int b = e >> 5, u = e & 31;
        uint4 v = *(const uint4*)&Dst[b * DPAD + u * 8];
        *(uint4*)(up + (size_t)b * (I_ * JM) + u * 8) = v;
    }
}

// ---------------------------------------------------------------------------
// shared squash-update epilogue: last CTA of batch b finalizes the pass
__device__ __forceinline__ void squash_epilogue(int b, float* s_acc, int* cnt,
                                                float pre_scale, int final_pass,
                                                float* out, int ny) {
    __threadfence();
    __shared__ int isLast;
    if (threadIdx.x == 0)
        isLast = (atomicAdd(&cnt[b], 1) == ny - 1);
    __syncthreads();
    if (!isLast) return;
    __threadfence();

    float s = *((volatile float*)&s_acc[b * JM + threadIdx.x]) * pre_scale;
    float n2 = s * s;
    #pragma unroll
    for (int off = 1; off < 16; off <<= 1)
        n2 += __shfl_xor_sync(0xffffffffu, n2, off);
    float v = n2 / (1.f + n2) * rsqrtf(n2 + 1e-8f) * s;

    if (final_pass) out[b * JM + threadIdx.x] = v;
    else            atomicAdd(&g_osum[b * JM + threadIdx.x], v);
}

// per-warp plain stores + cross-warp tree reduce + one global atomic / thread
__device__ __forceinline__ void reduce_epilogue(int b, float* s_acc,
                                                float (&ws)[WPC][JM],
                                                const float* acc,
                                                int wid, int lane) {
    float4* dst = (float4*)&ws[wid][lane * 8];
    dst[0] = make_float4(acc[0], acc[1], acc[2], acc[3]);
    dst[1] = make_float4(acc[4], acc[5], acc[6], acc[7]);
    __syncthreads();
    float tsum = 0.f;
    #pragma unroll
    for (int w = 0; w < WPC; w++) tsum += ws[w][threadIdx.x];
    atomicAdd(&s_acc[b * JM + threadIdx.x], tsum);
}

// ---------------------------------------------------------------------------
// K2: iteration 0 = uniform-c reduction: s0 = (1/16) sum_i u_hat; squash fused.
__global__ void __launch_bounds__(256) k_red0() {
    const int b    = blockIdx.x;
    const int wid  = threadIdx.x >> 5;
    const int lane = threadIdx.x & 31;

    __shared__ float ws[WPC][JM];

    const int i0 = blockIdx.y * 128 + wid * 16;
    const int4* base = (const int4*)(g_uhat + ((size_t)b * I_ + i0) * JM);

    float acc[8];
    #pragma unroll
    for (int k = 0; k < 8; k++) acc[k] = 0.f;
    #pragma unroll
    for (int blk = 0; blk < 4; blk++) {
        int4 v[4];
        #pragma unroll
        for (int r = 0; r < 4; r++)
            v[r] = base[(blk * 4 + r) * (JM / 8) + lane];
        #pragma unroll
        for (int r = 0; r < 4; r++) {
            const __half2* hp = (const __half2*)&v[r];
            #pragma unroll
            for (int q = 0; q < 4; q++) {
                float2 f = __half22float2(hp[q]);
                acc[2 * q] += f.x; acc[2 * q + 1] += f.y;
            }
        }
    }
    reduce_epilogue(b, g_scratch, ws, acc, wid, lane);
    squash_epilogue(b, g_scratch, g_counters, 1.f / 16.f, 0, nullptr, gridDim.y);
}

// ---------------------------------------------------------------------------
// K3: routing pass (iters 1,2): lane l owns (j=l>>1, m-half l&1),
// 8-wide batched softmax (ILP-8 shuffle/exp2 pipelines), 2 batches per warp.
__global__ void __launch_bounds__(256) k_route(float* __restrict__ s_acc,
                                               int* __restrict__ cnt,
                                               float* __restrict__ out,
                                               int final_pass) {
    const int b    = blockIdx.x;
    const int wid  = threadIdx.x >> 5;
    const int lane = threadIdx.x & 31;

    __shared__ float os[JM];
    __shared__ float ws[WPC][JM];
    os[threadIdx.x] = g_osum[b * JM + threadIdx.x];
    __syncthreads();

    const float L2E = 1.4426950408889634f;
    float o[8];
    #pragma unroll
    for (int k = 0; k < 8; k++) o[k] = os[lane * 8 + k] * L2E;

    float acc[8];
    #pragma unroll
    for (int k = 0; k < 8; k++) acc[k] = 0.f;

    const int i0 = (blockIdx.y * WPC + wid) * IW;
    const int4* base = (const int4*)(g_uhat + ((size_t)b * I_ + i0) * JM);

    #pragma unroll
    for (int batch = 0; batch < IW / 8; batch++) {
        int4 v[8];
        #pragma unroll
        for (int r = 0; r < 8; r++)
            v[r] = base[(batch * 8 + r) * (JM / 8) + lane];

        float p[8];
        #pragma unroll
        for (int r = 0; r < 8; r++) {
            const __half2* hp = (const __half2*)&v[r];
            float2 f0 = __half22float2(hp[0]), f1 = __half22float2(hp[1]);
            float2 f2 = __half22float2(hp[2]), f3 = __half22float2(hp[3]);
            p[r] = f0.x*o[0] + f0.y*o[1] + f1.x*o[2] + f1.y*o[3]
                 + f2.x*o[4] + f2.y*o[5] + f3.x*o[6] + f3.y*o[7];
        }
        #pragma unroll
        for (int r = 0; r < 8; r++) p[r] += __shfl_xor_sync(0xffffffffu, p[r], 1);
        #pragma unroll
        for (int r = 0; r < 8; r++) p[r] = exp2f(p[r]);
        float sum[8];
        #pragma unroll
        for (int r = 0; r < 8; r++) sum[r] = p[r];
        #pragma unroll
        for (int off = 2; off < 32; off <<= 1) {
            #pragma unroll
            for (int r = 0; r < 8; r++)
                sum[r] += __shfl_xor_sync(0xffffffffu, sum[r], off);
        }
        #pragma unroll
        for (int r = 0; r < 8; r++) {
            float c = __fdividef(p[r], sum[r]);
            const __half2* hp = (const __half2*)&v[r];
            float2 f0 = __half22float2(hp[0]), f1 = __half22float2(hp[1]);
            float2 f2 = __half22float2(hp[2]), f3 = __half22float2(hp[3]);
            acc[0] += c * f0.x; acc[1] += c * f0.y;
            acc[2] += c * f1.x; acc[3] += c * f1.y;
            acc[4] += c * f2.x; acc[5] += c * f2.y;
            acc[6] += c * f3.x; acc[7] += c * f3.y;
        }
    }

    reduce_epilogue(b, s_acc, ws, acc, wid, lane);
    squash_epilogue(b, s_acc, cnt, 1.f, final_pass, out, gridDim.y);
}

// ---------------------------------------------------------------------------
extern "C" void kernel_launch(void* const* d_in, const int* in_sizes, int n_in,
                              void* d_out, int out_size) {
    const float* inp = (const float*)d_in[0];   // [B, I, N]
    const float* W   = (const float*)d_in[1];   // [I, J, N, M]
    float* out = (float*)d_out;                 // [B, J, M]

    void *p_scr, *p_cnt, *p_os;
    cudaGetSymbolAddress(&p_scr, g_scratch);
    cudaGetSymbolAddress(&p_cnt, g_counters);
    cudaGetSymbolAddress(&p_os,  g_osum);
    cudaMemsetAsync(p_scr, 0, 3 * B_ * JM * sizeof(float));
    cudaMemsetAsync(p_cnt, 0, 3 * B_ * sizeof(int));
    cudaMemsetAsync(p_os,  0, B_ * JM * sizeof(float));

    float* s1 = (float*)p_scr + B_ * JM;
    float* s2 = (float*)p_scr + 2 * B_ * JM;
    int* c1 = (int*)p_cnt + B_;
    int* c2 = (int*)p_cnt + 2 * B_;

    dim3 rg(B_, CHUNKS);
    k_uhat<<<I_, 256>>>(inp, W);
    k_red0<<<dim3(B_, 16), 256>>>();            // iter 0 (uniform c) + squash
    k_route<<<rg, 256>>>(s1, c1, out, 0);       // iter 1
    k_route<<<rg, 256>>>(s2, c2, out, 1);       // iter 2 -> d_out
}